// round 2
// baseline (speedup 1.0000x reference)
#include <cuda_runtime.h>
#include <cstddef>

// Problem constants
#define NN    16
#define DIM   32
#define FEAT  192
#define KTOT  (DIM*FEAT)      // 6144
#define YSZ   (NN*DIM*FEAT)   // 98304

// Einsum tiling: CTA = 4 warps, all on the SAME 4 c's, each warp owns 8 f's.
#define CPC   4               // c's per CTA (and per warp)
#define FPW   8               // f's per warp
#define FPB   (FPW*4)         // 32 f's per CTA
#define NFS   (FEAT/FPB)      // 6  f-split groups
#define NCG   (FEAT/CPC)      // 48 c-groups

// Scratch (no allocations allowed -> device globals)
__device__ float g_xT [KTOT*NN];
__device__ float g_h1T[KTOT*NN];
__device__ float g_h2T[KTOT*NN];
__device__ float g_h1p[YSZ];
__device__ float g_ys [YSZ];   // layer accumulator, layout [c][n][m]

// ---------------------------------------------------------------------------
// Fused weighted einsum (f-major, raw-H staging, 4 c's per warp):
//   Ys[c][n][m] += sum_{e,f} H0T[(e*192+f)][n] * A0[f,c] * W[(e*192+f), c, m]
//   (+ the H1T/A1 stream when TWO_H)
// lane = m. Per e: 4 LDG.32 (w, one per c) + 4 LDS.128 (h pairs, shared by
// all 4 c's) + 4 FMUL (fold A) + 32 packed fma.rn.f32x2.
// ---------------------------------------------------------------------------
template<bool TWO_H>
__global__ void __launch_bounds__(128)
einsum_kernel(const float* __restrict__ W,
              const float* __restrict__ H0T, const float* __restrict__ A0,
              const float* __restrict__ H1T, const float* __restrict__ A1,
              float* __restrict__ Ys)
{
    const int c0     = blockIdx.x * CPC;
    const int fb_cta = blockIdx.y * FPB;
    const int tid    = threadIdx.x;
    const int w      = tid >> 5;
    const int lane   = tid & 31;

    // 32 KB buffer: per-warp raw-H staging during compute, reduction after.
    __shared__ __align__(16) unsigned long long sbuf[4096];
    __shared__ float sh_a0[FPB][CPC];
    __shared__ float sh_a1[FPB][CPC];

    // Stage the A sub-matrix for this CTA's (f-range x c-range).
    if (tid < FPB * CPC) {
        const int fi = tid / CPC, ci = tid % CPC;
        sh_a0[fi][ci] = A0[(fb_cta + fi) * FEAT + c0 + ci];
        if (TWO_H) sh_a1[fi][ci] = A1[(fb_cta + fi) * FEAT + c0 + ci];
    }
    __syncthreads();

    unsigned long long acc[CPC][8];
#pragma unroll
    for (int cc = 0; cc < CPC; ++cc)
#pragma unroll
        for (int p = 0; p < 8; ++p) acc[cc][p] = 0ull;

    float2* shh  = reinterpret_cast<float2*>(sbuf) + w * 256;          // [32e][8 pairs]
    float2* shh2 = reinterpret_cast<float2*>(sbuf) + 1024 + w * 256;   // TWO_H stream

    const size_t ES = (size_t)FEAT * FEAT * DIM;   // W stride for e+=1 (k += 192)
    const int fw = fb_cta + w * FPW;

    for (int fi = 0; fi < FPW; ++fi) {
        const int f = fw + fi;

        // ---- stage raw H rows for 32 e's (lane = e, 16 n's as 4 float4) ----
        {
            const float4* s0 = reinterpret_cast<const float4*>(
                H0T + (size_t)(lane * FEAT + f) * NN);
            float4* d0 = reinterpret_cast<float4*>(shh + lane * 8);
#pragma unroll
            for (int q = 0; q < 4; ++q) d0[q] = s0[q];
            if (TWO_H) {
                const float4* s1 = reinterpret_cast<const float4*>(
                    H1T + (size_t)(lane * FEAT + f) * NN);
                float4* d1 = reinterpret_cast<float4*>(shh2 + lane * 8);
#pragma unroll
                for (int q = 0; q < 4; ++q) d1[q] = s1[q];
            }
        }
        __syncwarp();

        float a0s[CPC], a1s[CPC];
#pragma unroll
        for (int cc = 0; cc < CPC; ++cc) {
            a0s[cc] = sh_a0[w * FPW + fi][cc];
            if (TWO_H) a1s[cc] = sh_a1[w * FPW + fi][cc];
        }

        const float* Wb = W + ((size_t)f * FEAT + c0) * DIM + lane;

        // software-pipelined e loop (lookahead 2)
        float w0[CPC], w1[CPC];
#pragma unroll
        for (int cc = 0; cc < CPC; ++cc) {
            w0[cc] = Wb[cc * DIM];
            w1[cc] = Wb[ES + cc * DIM];
        }

#pragma unroll
        for (int e = 0; e < 32; e += 2) {
            float n0[CPC], n1[CPC];
#pragma unroll
            for (int cc = 0; cc < CPC; ++cc) { n0[cc] = 0.f; n1[cc] = 0.f; }
            if (e < 30) {
                const float* Wp = Wb + (size_t)(e + 2) * ES;
#pragma unroll
                for (int cc = 0; cc < CPC; ++cc) {
                    n0[cc] = Wp[cc * DIM];
                    n1[cc] = Wp[ES + cc * DIM];
                }
            }
#pragma unroll
            for (int u = 0; u < 2; ++u) {
                const ulonglong2* hr =
                    reinterpret_cast<const ulonglong2*>(shh + (e + u) * 8);
                const ulonglong2 h0 = hr[0], h1 = hr[1], h2 = hr[2], h3 = hr[3];
                ulonglong2 g0, g1, g2, g3;
                if (TWO_H) {
                    const ulonglong2* gr =
                        reinterpret_cast<const ulonglong2*>(shh2 + (e + u) * 8);
                    g0 = gr[0]; g1 = gr[1]; g2 = gr[2]; g3 = gr[3];
                }
#pragma unroll
                for (int cc = 0; cc < CPC; ++cc) {
                    const float wraw = (u == 0) ? w0[cc] : w1[cc];
                    {
                        const float wv = wraw * a0s[cc];
                        unsigned long long wd;
                        asm("mov.b64 %0, {%1, %1};" : "=l"(wd) : "f"(wv));
                        asm("fma.rn.f32x2 %0, %1, %2, %0;" : "+l"(acc[cc][0]) : "l"(h0.x), "l"(wd));
                        asm("fma.rn.f32x2 %0, %1, %2, %0;" : "+l"(acc[cc][1]) : "l"(h0.y), "l"(wd));
                        asm("fma.rn.f32x2 %0, %1, %2, %0;" : "+l"(acc[cc][2]) : "l"(h1.x), "l"(wd));
                        asm("fma.rn.f32x2 %0, %1, %2, %0;" : "+l"(acc[cc][3]) : "l"(h1.y), "l"(wd));
                        asm("fma.rn.f32x2 %0, %1, %2, %0;" : "+l"(acc[cc][4]) : "l"(h2.x), "l"(wd));
                        asm("fma.rn.f32x2 %0, %1, %2, %0;" : "+l"(acc[cc][5]) : "l"(h2.y), "l"(wd));
                        asm("fma.rn.f32x2 %0, %1, %2, %0;" : "+l"(acc[cc][6]) : "l"(h3.x), "l"(wd));
                        asm("fma.rn.f32x2 %0, %1, %2, %0;" : "+l"(acc[cc][7]) : "l"(h3.y), "l"(wd));
                    }
                    if (TWO_H) {
                        const float wv1 = wraw * a1s[cc];
                        unsigned long long wd1;
                        asm("mov.b64 %0, {%1, %1};" : "=l"(wd1) : "f"(wv1));
                        asm("fma.rn.f32x2 %0, %1, %2, %0;" : "+l"(acc[cc][0]) : "l"(g0.x), "l"(wd1));
                        asm("fma.rn.f32x2 %0, %1, %2, %0;" : "+l"(acc[cc][1]) : "l"(g0.y), "l"(wd1));
                        asm("fma.rn.f32x2 %0, %1, %2, %0;" : "+l"(acc[cc][2]) : "l"(g1.x), "l"(wd1));
                        asm("fma.rn.f32x2 %0, %1, %2, %0;" : "+l"(acc[cc][3]) : "l"(g1.y), "l"(wd1));
                        asm("fma.rn.f32x2 %0, %1, %2, %0;" : "+l"(acc[cc][4]) : "l"(g2.x), "l"(wd1));
                        asm("fma.rn.f32x2 %0, %1, %2, %0;" : "+l"(acc[cc][5]) : "l"(g2.y), "l"(wd1));
                        asm("fma.rn.f32x2 %0, %1, %2, %0;" : "+l"(acc[cc][6]) : "l"(g3.x), "l"(wd1));
                        asm("fma.rn.f32x2 %0, %1, %2, %0;" : "+l"(acc[cc][7]) : "l"(g3.y), "l"(wd1));
                    }
                }
            }
#pragma unroll
            for (int cc = 0; cc < CPC; ++cc) { w0[cc] = n0[cc]; w1[cc] = n1[cc]; }
        }
        __syncwarp();
    }

    // ---- cross-warp reduction in smem (staging buffer reused), then atomics ----
    __syncthreads();
#pragma unroll
    for (int cc = 0; cc < CPC; ++cc)
#pragma unroll
        for (int p = 0; p < 8; ++p)
            sbuf[w * 1024 + cc * 256 + p * 32 + lane] = acc[cc][p];
    __syncthreads();

#pragma unroll
    for (int r = 0; r < 8; ++r) {
        const int idx = tid + r * 128;
        const unsigned long long v0 = sbuf[idx];
        const unsigned long long v1 = sbuf[idx + 1024];
        const unsigned long long v2 = sbuf[idx + 2048];
        const unsigned long long v3 = sbuf[idx + 3072];
        unsigned long long s01, s23, s;
        asm("add.rn.f32x2 %0, %1, %2;" : "=l"(s01) : "l"(v0), "l"(v1));
        asm("add.rn.f32x2 %0, %1, %2;" : "=l"(s23) : "l"(v2), "l"(v3));
        asm("add.rn.f32x2 %0, %1, %2;" : "=l"(s)   : "l"(s01), "l"(s23));
        float lo, hi;
        asm("mov.b64 {%0, %1}, %2;" : "=f"(lo), "=f"(hi) : "l"(s));
        const int cc = idx >> 8, p = (idx >> 5) & 7, m = idx & 31;
        float* yp = Ys + ((size_t)((c0 + cc) * NN + 2 * p)) * DIM + m;
        atomicAdd(yp,       lo);
        atomicAdd(yp + DIM, hi);
    }
}

// ---------------------------------------------------------------------------
// Plain transition matmul (layer init, overwrites Ys):
//   Ys[c][n][d] = sum_f H[(n,d)][f] * M[f][c]      (4 rows per block)
// ---------------------------------------------------------------------------
__global__ void __launch_bounds__(192)
matmul_kernel(const float* __restrict__ H, const float* __restrict__ M,
              float* __restrict__ Ys)
{
    __shared__ float shx[4][FEAT];
    const int r0 = blockIdx.x * 4;
    const int t  = threadIdx.x;
#pragma unroll
    for (int rr = 0; rr < 4; ++rr)
        shx[rr][t] = H[(size_t)(r0 + rr) * FEAT + t];
    __syncthreads();

    float a0 = 0.f, a1 = 0.f, a2 = 0.f, a3 = 0.f;
#pragma unroll 4
    for (int f = 0; f < FEAT; ++f) {
        const float mv = M[f * FEAT + t];
        a0 = fmaf(shx[0][f], mv, a0);
        a1 = fmaf(shx[1][f], mv, a1);
        a2 = fmaf(shx[2][f], mv, a2);
        a3 = fmaf(shx[3][f], mv, a3);
    }
    const float acc[4] = {a0, a1, a2, a3};
#pragma unroll
    for (int rr = 0; rr < 4; ++rr) {
        const int row = r0 + rr, n = row >> 5, d = row & 31;
        Ys[((size_t)t * NN + n) * DIM + d] = acc[rr];
    }
}

// ---------------------------------------------------------------------------
// Transpose x -> xT[k][n]
// ---------------------------------------------------------------------------
__global__ void transpose_kernel(const float* __restrict__ X,
                                 float* __restrict__ XT)
{
    const int idx = blockIdx.x * 256 + threadIdx.x;   // 384*256 = 98304 exact
    const int n = idx / KTOT, k = idx - n * KTOT;
    XT[(size_t)k * NN + n] = X[idx];
}

// ---------------------------------------------------------------------------
// LayerNorm over (m,c) for each n, reading Ys[c][n][m]. Writes optional
// plain layout [n][m][c] and/or transposed hT[(m*192+c)][n] for next einsum.
// (mean-of-terms division skipped: LN is scale-invariant)
// ---------------------------------------------------------------------------
__global__ void __launch_bounds__(384)
ln_kernel(const float* __restrict__ Ys, float* __restrict__ plainO,
          float* __restrict__ hTO)
{
    const int n = blockIdx.x, t = threadIdx.x;
    float vals[16];
    float s = 0.f, q = 0.f;
#pragma unroll
    for (int r = 0; r < 16; ++r) {
        const int i = t + r * 384;
        const float v = Ys[((i >> 5) << 9) + (n << 5) + (i & 31)];
        vals[r] = v;
        s += v;
        q = fmaf(v, v, q);
    }
#pragma unroll
    for (int o = 16; o > 0; o >>= 1) {
        s += __shfl_xor_sync(0xffffffffu, s, o);
        q += __shfl_xor_sync(0xffffffffu, q, o);
    }
    __shared__ float ss[12], qs[12];
    __shared__ float mean_b, rstd_b;
    const int wid = t >> 5, ln = t & 31;
    if (ln == 0) { ss[wid] = s; qs[wid] = q; }
    __syncthreads();
    if (t == 0) {
        float S = 0.f, Q = 0.f;
#pragma unroll
        for (int i = 0; i < 12; ++i) { S += ss[i]; Q += qs[i]; }
        const float mean = S * (1.0f / KTOT);
        const float var  = Q * (1.0f / KTOT) - mean * mean;
        mean_b = mean;
        rstd_b = rsqrtf(var + 1e-5f);
    }
    __syncthreads();
    const float mean = mean_b, rstd = rstd_b;
#pragma unroll
    for (int r = 0; r < 16; ++r) {
        const int i = t + r * 384;
        const float v = (vals[r] - mean) * rstd;
        const int c = i >> 5, m = i & 31;
        if (plainO) plainO[(size_t)n * KTOT + m * FEAT + c] = v;
        if (hTO)    hTO[(size_t)(m * FEAT + c) * NN + n]    = v;
    }
}

// ---------------------------------------------------------------------------
extern "C" void kernel_launch(void* const* d_in, const int* in_sizes, int n_in,
                              void* d_out, int out_size)
{
    const float* x   = (const float*)d_in[0];
    const float* s2t = (const float*)d_in[1];
    const float* t2s = (const float*)d_in[2];
    const float* s0  = (const float*)d_in[3];
    const float* s1  = (const float*)d_in[4];
    // d_in[5] = s2 : unused by the 4-layer schedule
    const float* t0  = (const float*)d_in[6];
    const float* t1  = (const float*)d_in[7];
    const float* t2  = (const float*)d_in[8];
    float* out = (float*)d_out;

    float *xT, *h1T, *h2T, *h1p, *ys;
    cudaGetSymbolAddress((void**)&xT,  g_xT);
    cudaGetSymbolAddress((void**)&h1T, g_h1T);
    cudaGetSymbolAddress((void**)&h2T, g_h2T);
    cudaGetSymbolAddress((void**)&h1p, g_h1p);
    cudaGetSymbolAddress((void**)&ys,  g_ys);

    const dim3 eg(NCG, NFS);   // 48 x 6 = 288 CTAs

    transpose_kernel<<<384, 256>>>(x, xT);

    // Layer 1: y1 = einsum(x, s2t, t0) -> LN -> h1 (plain + transposed)
    cudaMemsetAsync(ys, 0, YSZ * sizeof(float));
    einsum_kernel<false><<<eg, 128>>>(s2t, xT, t0, nullptr, nullptr, ys);
    ln_kernel<<<NN, 384>>>(ys, h1p, h1T);

    // Layer 2: y2 = x@s1 + einsum(h1, t2s, s0) -> LN -> h2 (transposed only)
    matmul_kernel<<<128, 192>>>(x, s1, ys);
    einsum_kernel<false><<<eg, 128>>>(t2s, h1T, s0, nullptr, nullptr, ys);
    ln_kernel<<<NN, 384>>>(ys, nullptr, h2T);

    // Layer 3: y3 = h1@t1 + einsum(x, s2t, t2) + einsum(h2, s2t, t0)
    //          (both s2t einsums fused into ONE pass over W) -> LN -> out
    matmul_kernel<<<128, 192>>>(h1p, t1, ys);
    einsum_kernel<true><<<eg, 128>>>(s2t, xT, t2, h2T, t0, ys);
    ln_kernel<<<NN, 384>>>(ys, out, nullptr);
}

// round 3
// speedup vs baseline: 1.6345x; 1.6345x over previous
#include <cuda_runtime.h>
#include <cstddef>

// Problem constants
#define NN    16
#define DIM   32
#define FEAT  192
#define KTOT  (DIM*FEAT)      // 6144
#define YSZ   (NN*DIM*FEAT)   // 98304

// Einsum tiling
#define CPC    4               // c's per warp (A folded into W scalar)
#define NCG    (FEAT/CPC)      // 48 c-groups
#define KSPLIT 8
#define KCTA   (KTOT/KSPLIT)   // 768
#define KWARP  (KCTA/4)        // 192
#define NSTAGE (KWARP/32)      // 6

// Scratch (no allocations allowed -> device globals)
__device__ float g_ybuf[YSZ];
__device__ float g_h1[YSZ];
__device__ float g_h2[YSZ];

// ---------------------------------------------------------------------------
// Fused weighted einsum (R1 skeleton + 4-way c reuse):
//   Y[n, m, c] += sum_k H0[n,k] * A0[k%192, c] * W[k, c, m]   (+ H1/A1 stream)
// W viewed as [KTOT][FEAT][DIM] (exactly s2t's / t2s's layout). lane = m.
// Raw H (c-independent) is staged in smem once per 32-k block; A is folded
// into the streamed W scalar by one FMUL per (k,c). Per k, the 4 broadcast
// LDS.128 of h-pairs are amortized over 4 c's.
// ---------------------------------------------------------------------------
template<bool TWO_H>
__global__ void __launch_bounds__(128)
einsum_kernel(const float* __restrict__ W,
              const float* __restrict__ H0, const float* __restrict__ A0,
              const float* __restrict__ H1, const float* __restrict__ A1,
              float* __restrict__ Y)
{
    const int ks   = blockIdx.x;           // 0..KSPLIT-1
    const int c0   = blockIdx.y * CPC;     // 0..191 step 4
    const int tid  = threadIdx.x;
    const int w    = tid >> 5;
    const int lane = tid & 31;

    // 32KB: h staging (two streams) during compute; reduction buffer after.
    __shared__ __align__(16) unsigned long long sbuf[4096];
    __shared__ float sh_a0[CPC][FEAT];
    __shared__ float sh_a1[CPC][FEAT];

    // Stage A columns for this CTA's 4 c's.
    for (int i = tid; i < CPC * FEAT; i += 128) {
        const int cc = i / FEAT, f = i - cc * FEAT;
        sh_a0[cc][f] = A0[f * FEAT + c0 + cc];
        if (TWO_H) sh_a1[cc][f] = A1[f * FEAT + c0 + cc];
    }
    __syncthreads();

    unsigned long long acc[CPC][8];
#pragma unroll
    for (int cc = 0; cc < CPC; ++cc)
#pragma unroll
        for (int p = 0; p < 8; ++p) acc[cc][p] = 0ull;

    float2* shh  = reinterpret_cast<float2*>(sbuf) + w * 256;          // [32k][8 pairs]
    float2* shh2 = reinterpret_cast<float2*>(sbuf) + 1024 + w * 256;   // TWO_H stream

    const int kwbase = ks * KCTA + w * KWARP;

    for (int s = 0; s < NSTAGE; ++s) {
        const int kb = kwbase + s * 32;
        const int fb = kb % FEAT;          // kb multiple of 32, 32|192 -> no wrap

        // ---- stage raw H for 32 k's: lane owns k = kb+lane, 16 n's ----
        {
            const float* hp0 = H0 + kb + lane;
#pragma unroll
            for (int p = 0; p < 8; ++p)
                shh[lane * 8 + p] = make_float2(hp0[(2 * p) * KTOT],
                                                hp0[(2 * p + 1) * KTOT]);
            if (TWO_H) {
                const float* hp1 = H1 + kb + lane;
#pragma unroll
                for (int p = 0; p < 8; ++p)
                    shh2[lane * 8 + p] = make_float2(hp1[(2 * p) * KTOT],
                                                     hp1[(2 * p + 1) * KTOT]);
            }
        }
        __syncwarp();

        const float* Wp = W + ((size_t)kb * FEAT + c0) * DIM + lane;

#pragma unroll 4
        for (int kk = 0; kk < 32; ++kk) {
            const ulonglong2* hr =
                reinterpret_cast<const ulonglong2*>(shh + kk * 8);
            const ulonglong2 h0 = hr[0], h1 = hr[1], h2 = hr[2], h3 = hr[3];
            ulonglong2 g0, g1, g2, g3;
            if (TWO_H) {
                const ulonglong2* gr =
                    reinterpret_cast<const ulonglong2*>(shh2 + kk * 8);
                g0 = gr[0]; g1 = gr[1]; g2 = gr[2]; g3 = gr[3];
            }
            const float* wrow = Wp + (size_t)kk * KTOT;
#pragma unroll
            for (int cc = 0; cc < CPC; ++cc) {
                const float wraw = wrow[cc * DIM];      // coalesced 128B/warp
                {
                    const float wv = wraw * sh_a0[cc][fb + kk];
                    unsigned long long wd;
                    asm("mov.b64 %0, {%1, %1};" : "=l"(wd) : "f"(wv));
                    asm("fma.rn.f32x2 %0, %1, %2, %0;" : "+l"(acc[cc][0]) : "l"(h0.x), "l"(wd));
                    asm("fma.rn.f32x2 %0, %1, %2, %0;" : "+l"(acc[cc][1]) : "l"(h0.y), "l"(wd));
                    asm("fma.rn.f32x2 %0, %1, %2, %0;" : "+l"(acc[cc][2]) : "l"(h1.x), "l"(wd));
                    asm("fma.rn.f32x2 %0, %1, %2, %0;" : "+l"(acc[cc][3]) : "l"(h1.y), "l"(wd));
                    asm("fma.rn.f32x2 %0, %1, %2, %0;" : "+l"(acc[cc][4]) : "l"(h2.x), "l"(wd));
                    asm("fma.rn.f32x2 %0, %1, %2, %0;" : "+l"(acc[cc][5]) : "l"(h2.y), "l"(wd));
                    asm("fma.rn.f32x2 %0, %1, %2, %0;" : "+l"(acc[cc][6]) : "l"(h3.x), "l"(wd));
                    asm("fma.rn.f32x2 %0, %1, %2, %0;" : "+l"(acc[cc][7]) : "l"(h3.y), "l"(wd));
                }
                if (TWO_H) {
                    const float wv1 = wraw * sh_a1[cc][fb + kk];
                    unsigned long long wd1;
                    asm("mov.b64 %0, {%1, %1};" : "=l"(wd1) : "f"(wv1));
                    asm("fma.rn.f32x2 %0, %1, %2, %0;" : "+l"(acc[cc][0]) : "l"(g0.x), "l"(wd1));
                    asm("fma.rn.f32x2 %0, %1, %2, %0;" : "+l"(acc[cc][1]) : "l"(g0.y), "l"(wd1));
                    asm("fma.rn.f32x2 %0, %1, %2, %0;" : "+l"(acc[cc][2]) : "l"(g1.x), "l"(wd1));
                    asm("fma.rn.f32x2 %0, %1, %2, %0;" : "+l"(acc[cc][3]) : "l"(g1.y), "l"(wd1));
                    asm("fma.rn.f32x2 %0, %1, %2, %0;" : "+l"(acc[cc][4]) : "l"(g2.x), "l"(wd1));
                    asm("fma.rn.f32x2 %0, %1, %2, %0;" : "+l"(acc[cc][5]) : "l"(g2.y), "l"(wd1));
                    asm("fma.rn.f32x2 %0, %1, %2, %0;" : "+l"(acc[cc][6]) : "l"(g3.x), "l"(wd1));
                    asm("fma.rn.f32x2 %0, %1, %2, %0;" : "+l"(acc[cc][7]) : "l"(g3.y), "l"(wd1));
                }
            }
        }
        __syncwarp();
    }

    // ---- cross-warp reduction (staging buffer reused), then atomics ----
    __syncthreads();
#pragma unroll
    for (int cc = 0; cc < CPC; ++cc)
#pragma unroll
        for (int p = 0; p < 8; ++p)
            sbuf[w * 1024 + cc * 256 + p * 32 + lane] = acc[cc][p];
    __syncthreads();

#pragma unroll
    for (int r = 0; r < 8; ++r) {
        const int idx = tid + r * 128;     // (cc, p, m)
        const unsigned long long v0 = sbuf[idx];
        const unsigned long long v1 = sbuf[idx + 1024];
        const unsigned long long v2 = sbuf[idx + 2048];
        const unsigned long long v3 = sbuf[idx + 3072];
        unsigned long long s01, s23, s;
        asm("add.rn.f32x2 %0, %1, %2;" : "=l"(s01) : "l"(v0), "l"(v1));
        asm("add.rn.f32x2 %0, %1, %2;" : "=l"(s23) : "l"(v2), "l"(v3));
        asm("add.rn.f32x2 %0, %1, %2;" : "=l"(s)   : "l"(s01), "l"(s23));
        float lo, hi;
        asm("mov.b64 {%0, %1}, %2;" : "=f"(lo), "=f"(hi) : "l"(s));
        const int cc = idx >> 8, p = (idx >> 5) & 7, m = idx & 31;
        float* yp = Y + ((size_t)(2 * p) * DIM + m) * FEAT + c0 + cc;
        atomicAdd(yp,                    lo);
        atomicAdd(yp + (size_t)DIM * FEAT, hi);
    }
}

// ---------------------------------------------------------------------------
// Plain transition matmul (R1 version): Y[row, c] = sum_f H[row, f] * M[f, c]
// Overwrites Y (initializes the layer accumulator); einsum atomicAdds on top.
// ---------------------------------------------------------------------------
__global__ void matmul_kernel(const float* __restrict__ H,
                              const float* __restrict__ M,
                              float* __restrict__ Y)
{
    __shared__ float sh[FEAT];
    const int row = blockIdx.x;
    const int t   = threadIdx.x;
    sh[t] = H[row * FEAT + t];
    __syncthreads();
    float s0 = 0.f, s1 = 0.f, s2 = 0.f, s3 = 0.f;
#pragma unroll 8
    for (int f = 0; f < FEAT; f += 4) {
        s0 = fmaf(sh[f    ], M[(f    ) * FEAT + t], s0);
        s1 = fmaf(sh[f + 1], M[(f + 1) * FEAT + t], s1);
        s2 = fmaf(sh[f + 2], M[(f + 2) * FEAT + t], s2);
        s3 = fmaf(sh[f + 3], M[(f + 3) * FEAT + t], s3);
    }
    Y[row * FEAT + t] = (s0 + s1) + (s2 + s3);
}

// ---------------------------------------------------------------------------
// LayerNorm over last two dims (6144 per n), eps=1e-5, no affine.
// (mean-over-terms division skipped: LN is scale-invariant)
// ---------------------------------------------------------------------------
__global__ void ln_kernel(const float* __restrict__ Y, float* __restrict__ O)
{
    const int n = blockIdx.x;
    const int t = threadIdx.x;
    const float* y = Y + (size_t)n * KTOT;

    float s = 0.f, q = 0.f;
    for (int i = t; i < KTOT; i += 384) {
        const float v = y[i];
        s += v;
        q = fmaf(v, v, q);
    }
#pragma unroll
    for (int o = 16; o > 0; o >>= 1) {
        s += __shfl_xor_sync(0xffffffffu, s, o);
        q += __shfl_xor_sync(0xffffffffu, q, o);
    }
    __shared__ float ss[12], qs[12];
    __shared__ float mean_b, rstd_b;
    const int wid = t >> 5, ln = t & 31;
    if (ln == 0) { ss[wid] = s; qs[wid] = q; }
    __syncthreads();
    if (t == 0) {
        float S = 0.f, Q = 0.f;
#pragma unroll
        for (int i = 0; i < 12; ++i) { S += ss[i]; Q += qs[i]; }
        const float mean = S * (1.0f / KTOT);
        const float var  = Q * (1.0f / KTOT) - mean * mean;
        mean_b = mean;
        rstd_b = rsqrtf(var + 1e-5f);
    }
    __syncthreads();
    const float mean = mean_b, rstd = rstd_b;
    for (int i = t; i < KTOT; i += 384)
        O[(size_t)n * KTOT + i] = (y[i] - mean) * rstd;
}

// ---------------------------------------------------------------------------
extern "C" void kernel_launch(void* const* d_in, const int* in_sizes, int n_in,
                              void* d_out, int out_size)
{
    const float* x   = (const float*)d_in[0];
    const float* s2t = (const float*)d_in[1];
    const float* t2s = (const float*)d_in[2];
    const float* s0  = (const float*)d_in[3];
    const float* s1  = (const float*)d_in[4];
    // d_in[5] = s2 : unused by the 4-layer schedule
    const float* t0  = (const float*)d_in[6];
    const float* t1  = (const float*)d_in[7];
    const float* t2  = (const float*)d_in[8];
    float* out = (float*)d_out;

    float *ybuf, *h1, *h2;
    cudaGetSymbolAddress((void**)&ybuf, g_ybuf);
    cudaGetSymbolAddress((void**)&h1,   g_h1);
    cudaGetSymbolAddress((void**)&h2,   g_h2);

    const dim3 eg(KSPLIT, NCG);   // 8 x 48 = 384 CTAs

    // Layer 1: y1 = einsum(x, s2t, t0) -> LN -> h1
    cudaMemsetAsync(ybuf, 0, YSZ * sizeof(float));
    einsum_kernel<false><<<eg, 128>>>(s2t, x, t0, nullptr, nullptr, ybuf);
    ln_kernel<<<NN, 384>>>(ybuf, h1);

    // Layer 2: y2 = x@s1 + einsum(h1, t2s, s0) -> LN -> h2
    matmul_kernel<<<NN * DIM, FEAT>>>(x, s1, ybuf);
    einsum_kernel<false><<<eg, 128>>>(t2s, h1, s0, nullptr, nullptr, ybuf);
    ln_kernel<<<NN, 384>>>(ybuf, h2);

    // Layer 3: y3 = h1@t1 + einsum(x, s2t, t2) + einsum(h2, s2t, t0)
    //          (both s2t einsums fused into ONE pass over W) -> LN -> out
    matmul_kernel<<<NN * DIM, FEAT>>>(h1, t1, ybuf);
    einsum_kernel<true><<<eg, 128>>>(s2t, x, t2, h2, t0, ybuf);
    ln_kernel<<<NN, 384>>>(ybuf, out);
}